// round 6
// baseline (speedup 1.0000x reference)
#include <cuda_runtime.h>
#include <math.h>

// Problem constants (fixed by the reference)
#define BT 4096
#define H  2048
#define V  32000

// GEMM tiling
#define BM 128
#define BN 128
#define BK 16
#define NCHUNK (V / BN)   // 250 vocab chunks
#define NTROW  (BT / BM)  // 32 token tiles

#define IGNORE_INDEX (-100)

// Scratch (allocation-free: __device__ globals)
__device__ float g_pm[NCHUNK * BT];   // partial max per (chunk, token)
__device__ float g_ps[NCHUNK * BT];   // partial sumexp per (chunk, token)
__device__ float g_tgt[BT];           // target logit per token
__device__ float g_sum;               // accumulated NLL sum
__device__ int   g_cnt;               // valid-token count
__device__ int   g_t64;               // 1 if target buffer is int64, 0 if int32

// Target loader that honors the detected layout. For int64 (little-endian),
// word 2t is the value and word 2t+1 is the (zero) high half.
__device__ __forceinline__ long long load_target(const void* tp, int t) {
    const int* p32 = (const int*)tp;
    if (g_t64) {
        long long lo = (long long)(unsigned int)p32[2 * t];
        long long hi = (long long)p32[2 * t + 1];
        return lo | (hi << 32);
    }
    return (long long)p32[t];
}

// Init + dtype detection. If the target tensor were int64 with values in
// [0, 2^31), every odd 32-bit word is zero; int32 random targets make many
// odd words nonzero. Reads stay within the smaller (int32) buffer size.
__global__ void init_kernel(const void* target_raw) {
    __shared__ int any_odd_nonzero;
    if (threadIdx.x == 0) any_odd_nonzero = 0;
    __syncthreads();

    const int* p32 = (const int*)target_raw;
    int local = 0;
    for (int i = threadIdx.x; i < BT / 2; i += blockDim.x) {
        if (p32[2 * i + 1] != 0) local = 1;
    }
    if (local) atomicOr(&any_odd_nonzero, 1);
    __syncthreads();

    if (threadIdx.x == 0) {
        g_t64 = any_odd_nonzero ? 0 : 1;
        g_sum = 0.0f;
        g_cnt = 0;
    }
}

// Stage 1: tiled fp32 GEMM (logits = x @ W^T + b) fused with per-chunk
// online softmax stats. Never materializes the full [BT,V] logits.
__global__ __launch_bounds__(256, 2)
void gemm_partial_kernel(const float* __restrict__ x,
                         const void* __restrict__ target_raw,
                         const float* __restrict__ w,
                         const float* __restrict__ bias)
{
    __shared__ float As[BK][BM];   // x tile, transposed: As[k][m]
    __shared__ float Bs[BK][BN];   // w tile, transposed: Bs[k][n]

    const int chunk = blockIdx.x;       // vocab tile index (0..249)
    const int trow  = blockIdx.y;       // token tile index (0..31)
    const int row0  = trow * BM;
    const int col0  = chunk * BN;

    const int tid = threadIdx.x;
    const int tx  = tid & 15;           // vocab-direction thread coord
    const int ty  = tid >> 4;           // token-direction thread coord

    float acc[8][8];
    #pragma unroll
    for (int i = 0; i < 8; i++)
        #pragma unroll
        for (int j = 0; j < 8; j++)
            acc[i][j] = 0.0f;

    for (int k0 = 0; k0 < H; k0 += BK) {
        // Cooperative load: 128 rows x 16 cols = 512 float4 per operand,
        // 2 float4 per thread per operand. f = m*4 + kq.
        #pragma unroll
        for (int q = 0; q < 2; q++) {
            const int f  = tid + q * 256;
            const int m  = f >> 2;
            const int kq = f & 3;
            float4 va = *(const float4*)(x + (size_t)(row0 + m) * H + k0 + kq * 4);
            As[kq * 4 + 0][m] = va.x;
            As[kq * 4 + 1][m] = va.y;
            As[kq * 4 + 2][m] = va.z;
            As[kq * 4 + 3][m] = va.w;
            float4 vb = *(const float4*)(w + (size_t)(col0 + m) * H + k0 + kq * 4);
            Bs[kq * 4 + 0][m] = vb.x;
            Bs[kq * 4 + 1][m] = vb.y;
            Bs[kq * 4 + 2][m] = vb.z;
            Bs[kq * 4 + 3][m] = vb.w;
        }
        __syncthreads();

        #pragma unroll
        for (int k = 0; k < BK; k++) {
            float a[8], b[8];
            *(float4*)(a)     = *(const float4*)&As[k][ty * 8];
            *(float4*)(a + 4) = *(const float4*)&As[k][ty * 8 + 4];
            *(float4*)(b)     = *(const float4*)&Bs[k][tx * 8];
            *(float4*)(b + 4) = *(const float4*)&Bs[k][tx * 8 + 4];
            #pragma unroll
            for (int i = 0; i < 8; i++)
                #pragma unroll
                for (int j = 0; j < 8; j++)
                    acc[i][j] = fmaf(a[i], b[j], acc[i][j]);
        }
        __syncthreads();
    }

    // Epilogue: bias add, target-logit capture, per-token (m, s) over this
    // 128-vocab chunk, reduced across the 16 tx threads of each token row.
    float bcol[8];
    #pragma unroll
    for (int j = 0; j < 8; j++)
        bcol[j] = bias[col0 + tx * 8 + j];

    #pragma unroll
    for (int i = 0; i < 8; i++) {
        const int t = row0 + ty * 8 + i;
        const long long tg = load_target(target_raw, t);

        float m = -INFINITY;
        #pragma unroll
        for (int j = 0; j < 8; j++) {
            float v = acc[i][j] + bcol[j];
            acc[i][j] = v;
            if ((long long)(col0 + tx * 8 + j) == tg)
                g_tgt[t] = v;
            m = fmaxf(m, v);
        }
        float s = 0.0f;
        #pragma unroll
        for (int j = 0; j < 8; j++)
            s += expf(acc[i][j] - m);

        // Reduce (m, s) across 16 lanes of this token row.
        // Warp layout: lane = (ty&1)*16 + tx -> width-16 groups are exact.
        #pragma unroll
        for (int off = 8; off >= 1; off >>= 1) {
            float m2 = __shfl_xor_sync(0xffffffffu, m, off, 16);
            float s2 = __shfl_xor_sync(0xffffffffu, s, off, 16);
            float mn = fmaxf(m, m2);
            s = s * expf(m - mn) + s2 * expf(m2 - mn);
            m = mn;
        }
        if (tx == 0) {
            g_pm[chunk * BT + t] = m;
            g_ps[chunk * BT + t] = s;
        }
    }
}

// Stage 2: merge 250 partial (m, s) per token -> lse -> per-token NLL ->
// block+atomic reduce of sum and valid count.
__global__ __launch_bounds__(256)
void reduce_kernel(const void* __restrict__ target_raw)
{
    const int t = blockIdx.x * blockDim.x + threadIdx.x;  // 0..4095

    float m = -INFINITY;
    float s = 0.0f;
    for (int c = 0; c < NCHUNK; c++) {
        float mc = g_pm[c * BT + t];
        float sc = g_ps[c * BT + t];
        float mn = fmaxf(m, mc);
        s = s * expf(m - mn) + sc * expf(mc - mn);
        m = mn;
    }
    const float lse = m + logf(s);

    const long long tg = load_target(target_raw, t);
    const int valid = (tg != (long long)IGNORE_INDEX) ? 1 : 0;
    float per = valid ? (lse - g_tgt[t]) : 0.0f;

    // Warp reduce, then one atomic per warp.
    #pragma unroll
    for (int off = 16; off >= 1; off >>= 1) {
        per += __shfl_xor_sync(0xffffffffu, per, off);
    }
    int vcnt = valid;
    #pragma unroll
    for (int off = 16; off >= 1; off >>= 1) {
        vcnt += __shfl_xor_sync(0xffffffffu, vcnt, off);
    }
    if ((threadIdx.x & 31) == 0) {
        atomicAdd(&g_sum, per);
        atomicAdd(&g_cnt, vcnt);
    }
}

__global__ void finalize_kernel(float* __restrict__ out)
{
    int c = g_cnt;
    if (c < 1) c = 1;
    out[0] = g_sum / (float)c;
}

extern "C" void kernel_launch(void* const* d_in, const int* in_sizes, int n_in,
                              void* d_out, int out_size)
{
    const float* x          = (const float*)d_in[0];
    const void*  target_raw = d_in[1];
    const float* w          = (const float*)d_in[2];
    const float* bias       = (const float*)d_in[3];
    float*       out        = (float*)d_out;

    init_kernel<<<1, 256>>>(target_raw);
    dim3 grid(NCHUNK, NTROW);
    gemm_partial_kernel<<<grid, 256>>>(x, target_raw, w, bias);
    reduce_kernel<<<BT / 256, 256>>>(target_raw);
    finalize_kernel<<<1, 1>>>(out);
}

// round 11
// speedup vs baseline: 8.1838x; 8.1838x over previous
#include <cuda_runtime.h>
#include <cuda_bf16.h>
#include <math.h>
#include <stdint.h>

// Problem constants
#define BT 4096
#define H  2048
#define V  32000

// GEMM tiling
#define BM 128
#define BN 128
#define BK 64                   // K elems per stage (128 B of bf16 per row)
#define NSTAGE 3
#define NK (H / BK)             // 32 K-chunks
#define NCH (V / BN)            // 250 vocab chunks
#define NTR (BT / BM)           // 32 token tiles
#define IGNORE_INDEX (-100)

// SMEM: 3 stages x (A 16KB + B 16KB) + bias + partial arrays
#define STAGE_BYTES 32768
#define OFF_BIAS    (NSTAGE * STAGE_BYTES)          // 98304
#define OFF_PM      (OFF_BIAS + 512)
#define OFF_PS      (OFF_PM + 4 * 128 * 4)
#define SMEM_DYN    (OFF_PS + 4 * 128 * 4)          // 102912

// ------------------------- device scratch (allocation-free) -----------------
__device__ __nv_bfloat16 g_xb[(size_t)BT * H];      // 16 MB
__device__ __nv_bfloat16 g_wb[(size_t)V * H];       // 128 MB
__device__ float g_pm[NCH * BT];
__device__ float g_ps[NCH * BT];
__device__ float g_tgt[BT];
__device__ float g_sum;
__device__ int   g_cnt;
__device__ int   g_t64;

// ------------------------- small asm helpers --------------------------------
__device__ __forceinline__ uint32_t smem_u32(const void* p) {
    uint32_t a;
    asm("{ .reg .u64 t; cvta.to.shared.u64 t, %1; cvt.u32.u64 %0, t; }"
        : "=r"(a) : "l"(p));
    return a;
}

__device__ __forceinline__ void cp_async16(uint32_t saddr, const void* gaddr) {
    asm volatile("cp.async.cg.shared.global [%0], [%1], 16;"
                 :: "r"(saddr), "l"(gaddr) : "memory");
}
__device__ __forceinline__ void cp_commit() {
    asm volatile("cp.async.commit_group;" ::: "memory");
}
template <int N>
__device__ __forceinline__ void cp_wait() {
    asm volatile("cp.async.wait_group %0;" :: "n"(N) : "memory");
}

__device__ __forceinline__ void ldm_x4(uint32_t* r, uint32_t addr) {
    asm volatile("ldmatrix.sync.aligned.m8n8.x4.shared.b16 {%0,%1,%2,%3}, [%4];"
                 : "=r"(r[0]), "=r"(r[1]), "=r"(r[2]), "=r"(r[3]) : "r"(addr));
}

__device__ __forceinline__ void mma_bf16(float* d, const uint32_t* a,
                                         uint32_t b0, uint32_t b1) {
    asm volatile(
        "mma.sync.aligned.m16n8k16.row.col.f32.bf16.bf16.f32 "
        "{%0,%1,%2,%3}, {%4,%5,%6,%7}, {%8,%9}, {%0,%1,%2,%3};"
        : "+f"(d[0]), "+f"(d[1]), "+f"(d[2]), "+f"(d[3])
        : "r"(a[0]), "r"(a[1]), "r"(a[2]), "r"(a[3]), "r"(b0), "r"(b1));
}

// ------------------------- target dtype handling ----------------------------
__device__ __forceinline__ long long load_target(const void* tp, int t) {
    const int* p32 = (const int*)tp;
    if (g_t64) {
        long long lo = (long long)(unsigned int)p32[2 * t];
        long long hi = (long long)p32[2 * t + 1];
        return lo | (hi << 32);
    }
    return (long long)p32[t];
}

__global__ void init_kernel(const void* target_raw) {
    __shared__ int any_odd;
    if (threadIdx.x == 0) any_odd = 0;
    __syncthreads();
    const int* p32 = (const int*)target_raw;
    int local = 0;
    for (int i = threadIdx.x; i < BT / 2; i += blockDim.x)
        if (p32[2 * i + 1] != 0) local = 1;
    if (local) atomicOr(&any_odd, 1);
    __syncthreads();
    if (threadIdx.x == 0) {
        g_t64 = any_odd ? 0 : 1;
        g_sum = 0.0f;
        g_cnt = 0;
    }
}

// ------------------------- fp32 -> bf16 conversion --------------------------
__global__ __launch_bounds__(256)
void convert_kernel(const float* __restrict__ src, __nv_bfloat16* __restrict__ dst, int n8)
{
    int i = blockIdx.x * blockDim.x + threadIdx.x;
    if (i >= n8) return;
    const float4* s4 = (const float4*)src;
    float4 a = s4[2 * i];
    float4 b = s4[2 * i + 1];
    __nv_bfloat162 p0 = __float22bfloat162_rn(make_float2(a.x, a.y));
    __nv_bfloat162 p1 = __float22bfloat162_rn(make_float2(a.z, a.w));
    __nv_bfloat162 p2 = __float22bfloat162_rn(make_float2(b.x, b.y));
    __nv_bfloat162 p3 = __float22bfloat162_rn(make_float2(b.z, b.w));
    uint4 o;
    o.x = *(const uint32_t*)&p0;
    o.y = *(const uint32_t*)&p1;
    o.z = *(const uint32_t*)&p2;
    o.w = *(const uint32_t*)&p3;
    ((uint4*)dst)[i] = o;
}

// ------------------------- main GEMM + partial-LSE kernel -------------------
// CTA: 128 tokens x 128 vocab. 8 warps = 2(m) x 4(n); warp tile 64x32.
// mma.sync m16n8k16 bf16, cp.async 3-stage pipeline, swizzled smem.
__global__ __launch_bounds__(256, 2)
void gemm_kernel(const void* __restrict__ target_raw,
                 const float* __restrict__ bias)
{
    extern __shared__ char smem[];
    const uint32_t sb = smem_u32(smem);

    const int tid  = threadIdx.x;
    const int wid  = tid >> 5;
    const int lane = tid & 31;
    const int wm   = wid >> 2;        // 0..1 : token half
    const int wn   = wid & 3;         // 0..3 : vocab quarter
    const int trow = blockIdx.x;
    const int chnk = blockIdx.y;
    const int row0 = trow * BM;
    const int col0 = chnk * BN;

    // bias tile -> smem
    float* sbias = (float*)(smem + OFF_BIAS);
    if (tid < 128) sbias[tid] = bias[col0 + tid];

    // global load mapping: 1024 16B-chunks per operand per stage; 4 per thread
    // idx = tid + 256*q ; row = idx>>3 (0..127) ; c = idx&7 (16B chunk in row)
    const __nv_bfloat16* gA = g_xb + (size_t)row0 * H;
    const __nv_bfloat16* gW = g_wb + (size_t)col0 * H;

    // per-thread swizzled smem store offsets (same for A and B within a stage)
    uint32_t st_off[4];
    #pragma unroll
    for (int q = 0; q < 4; q++) {
        const int idx = tid + 256 * q;
        const int r = idx >> 3;
        const int c = idx & 7;
        st_off[q] = (uint32_t)(r * 128 + ((c ^ (r & 7)) << 4));
    }

    auto issue_loads = [&](int kchunk, int slot) {
        const uint32_t aBase = sb + (uint32_t)slot * STAGE_BYTES;
        const uint32_t bBase = aBase + 16384u;
        const int k0 = kchunk * BK;
        #pragma unroll
        for (int q = 0; q < 4; q++) {
            const int idx = tid + 256 * q;
            const int r = idx >> 3;
            const int c = idx & 7;
            cp_async16(aBase + st_off[q], gA + (size_t)r * H + k0 + c * 8);
            cp_async16(bBase + st_off[q], gW + (size_t)r * H + k0 + c * 8);
        }
    };

    // ldmatrix row bases (per thread)
    int arow[4], brow[2];
    #pragma unroll
    for (int mt = 0; mt < 4; mt++) arow[mt] = wm * 64 + mt * 16 + (lane & 15);
    #pragma unroll
    for (int ng = 0; ng < 2; ng++) brow[ng] = wn * 32 + ng * 16 + (lane & 15);
    const int kc_lane = lane >> 4;    // 0/1: which 16B chunk within k16

    float acc[4][4][4];               // [mt][nt][frag]
    #pragma unroll
    for (int i = 0; i < 4; i++)
        #pragma unroll
        for (int j = 0; j < 4; j++)
            #pragma unroll
            for (int c = 0; c < 4; c++)
                acc[i][j][c] = 0.0f;

    // pipeline prologue
    issue_loads(0, 0); cp_commit();
    issue_loads(1, 1); cp_commit();

    for (int ki = 0; ki < NK; ki++) {
        cp_wait<1>();
        __syncthreads();

        if (ki + 2 < NK) issue_loads(ki + 2, (ki + 2) % NSTAGE);
        cp_commit();

        const uint32_t aBase = sb + (uint32_t)(ki % NSTAGE) * STAGE_BYTES;
        const uint32_t bBase = aBase + 16384u;

        #pragma unroll
        for (int ks = 0; ks < 4; ks++) {          // four k16 steps in BK=64
            const int kc = ks * 2 + kc_lane;
            uint32_t af[4][4], bf[2][4];
            #pragma unroll
            for (int mt = 0; mt < 4; mt++) {
                const uint32_t a = aBase + (uint32_t)(arow[mt] * 128 +
                                   ((kc ^ (arow[mt] & 7)) << 4));
                ldm_x4(af[mt], a);
            }
            #pragma unroll
            for (int ng = 0; ng < 2; ng++) {
                const uint32_t b = bBase + (uint32_t)(brow[ng] * 128 +
                                   ((kc ^ (brow[ng] & 7)) << 4));
                ldm_x4(bf[ng], b);
            }
            #pragma unroll
            for (int mt = 0; mt < 4; mt++) {
                #pragma unroll
                for (int nt = 0; nt < 4; nt++) {
                    const int ng = nt >> 1, hh = nt & 1;
                    mma_bf16(acc[mt][nt], af[mt], bf[ng][hh], bf[ng][hh + 2]);
                }
            }
        }
        __syncthreads();
    }

    // ---- epilogue: bias, target capture, per-row (m,s) --------------------
    const int g  = lane >> 2;
    const int tc = lane & 3;

    float bv[4][2];
    #pragma unroll
    for (int nt = 0; nt < 4; nt++) {
        const int cl = wn * 32 + nt * 8 + tc * 2;
        bv[nt][0] = sbias[cl];
        bv[nt][1] = sbias[cl + 1];
    }

    float* spm = (float*)(smem + OFF_PM);   // [4][128]
    float* sps = (float*)(smem + OFF_PS);

    #pragma unroll
    for (int mt = 0; mt < 4; mt++) {
        #pragma unroll
        for (int hh = 0; hh < 2; hh++) {
            const int rloc = wm * 64 + mt * 16 + g + 8 * hh;
            const int t = row0 + rloc;
            const long long tg = load_target(target_raw, t);

            float v[8];
            float m = -INFINITY;
            #pragma unroll
            for (int nt = 0; nt < 4; nt++) {
                #pragma unroll
                for (int cc = 0; cc < 2; cc++) {
                    const float val = acc[mt][nt][hh * 2 + cc] + bv[nt][cc];
                    v[nt * 2 + cc] = val;
                    m = fmaxf(m, val);
                    const long long cg = (long long)(col0 + wn * 32 + nt * 8 + tc * 2 + cc);
                    if (cg == tg) g_tgt[t] = val;
                }
            }
            float s = 0.0f;
            #pragma unroll
            for (int j = 0; j < 8; j++)
                s += __expf(v[j] - m);

            // reduce across the 4 lanes of the quad (same row)
            #pragma unroll
            for (int off = 1; off <= 2; off <<= 1) {
                float m2 = __shfl_xor_sync(0xffffffffu, m, off);
                float s2 = __shfl_xor_sync(0xffffffffu, s, off);
                float mn = fmaxf(m, m2);
                s = s * __expf(m - mn) + s2 * __expf(m2 - mn);
                m = mn;
            }
            if (tc == 0) {
                spm[wn * 128 + rloc] = m;
                sps[wn * 128 + rloc] = s;
            }
        }
    }
    __syncthreads();

    // merge 4 warp-column partials per row -> global partials
    if (tid < 128) {
        float m = spm[tid], s = sps[tid];
        #pragma unroll
        for (int w = 1; w < 4; w++) {
            float m2 = spm[w * 128 + tid];
            float s2 = sps[w * 128 + tid];
            float mn = fmaxf(m, m2);
            s = s * __expf(m - mn) + s2 * __expf(m2 - mn);
            m = mn;
        }
        g_pm[chnk * BT + row0 + tid] = m;
        g_ps[chnk * BT + row0 + tid] = s;
    }
}

// ------------------------- stage 2: merge + reduce --------------------------
__global__ __launch_bounds__(256)
void reduce_kernel(const void* __restrict__ target_raw)
{
    const int t = blockIdx.x * blockDim.x + threadIdx.x;

    float m = -INFINITY, s = 0.0f;
    for (int c = 0; c < NCH; c++) {
        float mc = g_pm[c * BT + t];
        float sc = g_ps[c * BT + t];
        float mn = fmaxf(m, mc);
        s = s * expf(m - mn) + sc * expf(mc - mn);
        m = mn;
    }
    const float lse = m + logf(s);

    const long long tg = load_target(target_raw, t);
    const int valid = (tg != (long long)IGNORE_INDEX) ? 1 : 0;
    float per = valid ? (lse - g_tgt[t]) : 0.0f;

    #pragma unroll
    for (int off = 16; off >= 1; off >>= 1)
        per += __shfl_xor_sync(0xffffffffu, per, off);
    int vc = valid;
    #pragma unroll
    for (int off = 16; off >= 1; off >>= 1)
        vc += __shfl_xor_sync(0xffffffffu, vc, off);
    if ((threadIdx.x & 31) == 0) {
        atomicAdd(&g_sum, per);
        atomicAdd(&g_cnt, vc);
    }
}

__global__ void finalize_kernel(float* __restrict__ out)
{
    int c = g_cnt;
    if (c < 1) c = 1;
    out[0] = g_sum / (float)c;
}

// ------------------------- host launch --------------------------------------
extern "C" void kernel_launch(void* const* d_in, const int* in_sizes, int n_in,
                              void* d_out, int out_size)
{
    const float* x          = (const float*)d_in[0];
    const void*  target_raw = d_in[1];
    const float* w          = (const float*)d_in[2];
    const float* bias       = (const float*)d_in[3];
    float*       out        = (float*)d_out;

    void *xb = nullptr, *wb = nullptr;
    cudaGetSymbolAddress(&xb, g_xb);
    cudaGetSymbolAddress(&wb, g_wb);

    cudaFuncSetAttribute(gemm_kernel, cudaFuncAttributeMaxDynamicSharedMemorySize,
                         SMEM_DYN);

    {
        int n8 = (BT * H) / 8;
        convert_kernel<<<(n8 + 255) / 256, 256>>>(x, (__nv_bfloat16*)xb, n8);
    }
    {
        int n8 = (int)(((size_t)V * H) / 8);
        convert_kernel<<<(n8 + 255) / 256, 256>>>(w, (__nv_bfloat16*)wb, n8);
    }

    init_kernel<<<1, 256>>>(target_raw);

    dim3 grid(NTR, NCH);
    gemm_kernel<<<grid, 256, SMEM_DYN>>>(target_raw, bias);

    reduce_kernel<<<BT / 256, 256>>>(target_raw);
    finalize_kernel<<<1, 1>>>(out);
}

// round 14
// speedup vs baseline: 8.2768x; 1.0114x over previous
#include <cuda_runtime.h>
#include <cuda_bf16.h>
#include <math.h>
#include <stdint.h>

// Problem constants
#define BT 4096
#define H  2048
#define V  32000

// GEMM tiling
#define BM 128
#define BN 128
#define BK 64                   // K elems per stage (128 B of bf16 per row)
#define NSTAGE 3
#define NK (H / BK)             // 32 K-chunks
#define NCH (V / BN)            // 250 vocab chunks
#define NTR (BT / BM)           // 32 token tiles
#define IGNORE_INDEX (-100)

// SMEM: 3 stages x (A 16KB + B 16KB) + bias + partial arrays
#define STAGE_BYTES 32768
#define OFF_BIAS    (NSTAGE * STAGE_BYTES)          // 98304
#define OFF_PM      (OFF_BIAS + 512)
#define OFF_PS      (OFF_PM + 4 * 128 * 4)
#define SMEM_DYN    (OFF_PS + 4 * 128 * 4)          // 102912

// ------------------------- device scratch (allocation-free) -----------------
__device__ __nv_bfloat16 g_xb[(size_t)BT * H];      // 16 MB
__device__ __nv_bfloat16 g_wb[(size_t)V * H];       // 128 MB
__device__ float g_pm[NCH * BT];
__device__ float g_ps[NCH * BT];
__device__ float g_tgt[BT];
__device__ float g_sum;
__device__ int   g_cnt;
__device__ int   g_t64;

// ------------------------- small asm helpers --------------------------------
__device__ __forceinline__ uint32_t smem_u32(const void* p) {
    uint32_t a;
    asm("{ .reg .u64 t; cvta.to.shared.u64 t, %1; cvt.u32.u64 %0, t; }"
        : "=r"(a) : "l"(p));
    return a;
}

__device__ __forceinline__ void cp_async16(uint32_t saddr, const void* gaddr) {
    asm volatile("cp.async.cg.shared.global [%0], [%1], 16;"
                 :: "r"(saddr), "l"(gaddr) : "memory");
}
__device__ __forceinline__ void cp_commit() {
    asm volatile("cp.async.commit_group;" ::: "memory");
}
template <int N>
__device__ __forceinline__ void cp_wait() {
    asm volatile("cp.async.wait_group %0;" :: "n"(N) : "memory");
}

__device__ __forceinline__ void ldm_x4(uint32_t* r, uint32_t addr) {
    asm volatile("ldmatrix.sync.aligned.m8n8.x4.shared.b16 {%0,%1,%2,%3}, [%4];"
                 : "=r"(r[0]), "=r"(r[1]), "=r"(r[2]), "=r"(r[3]) : "r"(addr));
}

__device__ __forceinline__ void mma_bf16(float* d, const uint32_t* a,
                                         uint32_t b0, uint32_t b1) {
    asm volatile(
        "mma.sync.aligned.m16n8k16.row.col.f32.bf16.bf16.f32 "
        "{%0,%1,%2,%3}, {%4,%5,%6,%7}, {%8,%9}, {%0,%1,%2,%3};"
        : "+f"(d[0]), "+f"(d[1]), "+f"(d[2]), "+f"(d[3])
        : "r"(a[0]), "r"(a[1]), "r"(a[2]), "r"(a[3]), "r"(b0), "r"(b1));
}

// ------------------------- target dtype handling ----------------------------
__device__ __forceinline__ long long load_target(const void* tp, int t) {
    const int* p32 = (const int*)tp;
    if (g_t64) {
        long long lo = (long long)(unsigned int)p32[2 * t];
        long long hi = (long long)p32[2 * t + 1];
        return lo | (hi << 32);
    }
    return (long long)p32[t];
}

__global__ void init_kernel(const void* target_raw) {
    __shared__ int any_odd;
    if (threadIdx.x == 0) any_odd = 0;
    __syncthreads();
    const int* p32 = (const int*)target_raw;
    int local = 0;
    for (int i = threadIdx.x; i < BT / 2; i += blockDim.x)
        if (p32[2 * i + 1] != 0) local = 1;
    if (local) atomicOr(&any_odd, 1);
    __syncthreads();
    if (threadIdx.x == 0) {
        g_t64 = any_odd ? 0 : 1;
        g_sum = 0.0f;
        g_cnt = 0;
    }
}

// ------------------------- fp32 -> bf16 conversion --------------------------
__global__ __launch_bounds__(256)
void convert_kernel(const float* __restrict__ src, __nv_bfloat16* __restrict__ dst, int n8)
{
    int i = blockIdx.x * blockDim.x + threadIdx.x;
    if (i >= n8) return;
    const float4* s4 = (const float4*)src;
    float4 a = s4[2 * i];
    float4 b = s4[2 * i + 1];
    __nv_bfloat162 p0 = __float22bfloat162_rn(make_float2(a.x, a.y));
    __nv_bfloat162 p1 = __float22bfloat162_rn(make_float2(a.z, a.w));
    __nv_bfloat162 p2 = __float22bfloat162_rn(make_float2(b.x, b.y));
    __nv_bfloat162 p3 = __float22bfloat162_rn(make_float2(b.z, b.w));
    uint4 o;
    o.x = *(const uint32_t*)&p0;
    o.y = *(const uint32_t*)&p1;
    o.z = *(const uint32_t*)&p2;
    o.w = *(const uint32_t*)&p3;
    ((uint4*)dst)[i] = o;
}

// ------------------------- main GEMM + partial-LSE kernel -------------------
// CTA: 128 tokens x 128 vocab. 8 warps = 2(m) x 4(n); warp tile 64x32.
// mma.sync m16n8k16 bf16, cp.async 3-stage pipeline, swizzled smem.
// One barrier per K-iteration (trailing barrier proven redundant: loads at
// iter ki target slot (ki-1)%3, whose readers all passed the top barrier).
__global__ __launch_bounds__(256, 2)
void gemm_kernel(const void* __restrict__ target_raw,
                 const float* __restrict__ bias)
{
    extern __shared__ char smem[];
    const uint32_t sb = smem_u32(smem);

    const int tid  = threadIdx.x;
    const int wid  = tid >> 5;
    const int lane = tid & 31;
    const int wm   = wid >> 2;        // 0..1 : token half
    const int wn   = wid & 3;         // 0..3 : vocab quarter
    const int trow = blockIdx.x;
    const int chnk = blockIdx.y;
    const int row0 = trow * BM;
    const int col0 = chnk * BN;

    // bias tile -> smem
    float* sbias = (float*)(smem + OFF_BIAS);
    if (tid < 128) sbias[tid] = bias[col0 + tid];

    // Cooperative-load addressing with constant offsets:
    // idx = tid + 256q -> r = (tid>>3) + 32q, c = tid&7 exactly.
    // Global: base + q*32*H*2 = q*131072 bytes; advance +128 B per K-chunk.
    // Smem:   st0 + q*32*128 = q*4096 bytes (swizzle term constant in q).
    const int r0q = tid >> 3;
    const int c0q = tid & 7;
    const char* gAt = (const char*)(g_xb + (size_t)(row0 + r0q) * H) + c0q * 16;
    const char* gWt = (const char*)(g_wb + (size_t)(col0 + r0q) * H) + c0q * 16;
    const uint32_t st0 = (uint32_t)(r0q * 128 + ((c0q ^ (r0q & 7)) << 4));

    auto issue_loads = [&](int kchunk, int slot) {
        const uint32_t aB = sb + (uint32_t)slot * STAGE_BYTES + st0;
        const uint32_t bB = aB + 16384u;
        const char* pa = gAt + kchunk * (BK * 2);
        const char* pb = gWt + kchunk * (BK * 2);
        #pragma unroll
        for (int q = 0; q < 4; q++) {
            cp_async16(aB + q * 4096u, pa + q * 131072);
            cp_async16(bB + q * 4096u, pb + q * 131072);
        }
    };

    // ldmatrix addressing with constant offsets:
    // arow&7 == brow&7 == lane&7 for every mt/ng, so the swizzle term
    // ((kc ^ (lane&7))<<4) is shared; mt/ng contribute immediates (*2048).
    const int l7      = lane & 7;
    const int kc_lane = lane >> 4;
    const uint32_t arowbase = (uint32_t)((wm * 64 + (lane & 15)) * 128);
    const uint32_t browbase = (uint32_t)((wn * 32 + (lane & 15)) * 128);

    float acc[4][4][4];               // [mt][nt][frag]
    #pragma unroll
    for (int i = 0; i < 4; i++)
        #pragma unroll
        for (int j = 0; j < 4; j++)
            #pragma unroll
            for (int c = 0; c < 4; c++)
                acc[i][j][c] = 0.0f;

    // pipeline prologue
    issue_loads(0, 0); cp_commit();
    issue_loads(1, 1); cp_commit();

    for (int ki = 0; ki < NK; ki++) {
        cp_wait<1>();
        __syncthreads();

        if (ki + 2 < NK) issue_loads(ki + 2, (ki + 2) % NSTAGE);
        cp_commit();

        const uint32_t aBase = sb + (uint32_t)(ki % NSTAGE) * STAGE_BYTES;
        const uint32_t bBase = aBase + 16384u;

        #pragma unroll
        for (int ks = 0; ks < 4; ks++) {          // four k16 steps in BK=64
            const uint32_t ch = (uint32_t)(((ks * 2 + kc_lane) ^ l7) << 4);
            uint32_t af[4][4], bf[2][4];
            const uint32_t aAddr = aBase + arowbase + ch;
            ldm_x4(af[0], aAddr);
            ldm_x4(af[1], aAddr + 2048u);
            ldm_x4(af[2], aAddr + 4096u);
            ldm_x4(af[3], aAddr + 6144u);
            const uint32_t bAddr = bBase + browbase + ch;
            ldm_x4(bf[0], bAddr);
            ldm_x4(bf[1], bAddr + 2048u);
            #pragma unroll
            for (int mt = 0; mt < 4; mt++) {
                #pragma unroll
                for (int nt = 0; nt < 4; nt++) {
                    const int ng = nt >> 1, hh = nt & 1;
                    mma_bf16(acc[mt][nt], af[mt], bf[ng][hh], bf[ng][hh + 2]);
                }
            }
        }
        // no trailing barrier: next iteration's top barrier orders the
        // slot reuse (see proof in kernel comment)
    }

    // ---- epilogue: bias, target capture, per-row (m,s) --------------------
    const int g  = lane >> 2;
    const int tc = lane & 3;

    float bv[4][2];
    #pragma unroll
    for (int nt = 0; nt < 4; nt++) {
        const int cl = wn * 32 + nt * 8 + tc * 2;
        bv[nt][0] = sbias[cl];
        bv[nt][1] = sbias[cl + 1];
    }

    float* spm = (float*)(smem + OFF_PM);   // [4][128]
    float* sps = (float*)(smem + OFF_PS);

    #pragma unroll
    for (int mt = 0; mt < 4; mt++) {
        #pragma unroll
        for (int hh = 0; hh < 2; hh++) {
            const int rloc = wm * 64 + mt * 16 + g + 8 * hh;
            const int t = row0 + rloc;
            const long long tg = load_target(target_raw, t);

            float v[8];
            float m = -INFINITY;
            #pragma unroll
            for (int nt = 0; nt < 4; nt++) {
                #pragma unroll
                for (int cc = 0; cc < 2; cc++) {
                    const float val = acc[mt][nt][hh * 2 + cc] + bv[nt][cc];
                    v[nt * 2 + cc] = val;
                    m = fmaxf(m, val);
                    const long long cg = (long long)(col0 + wn * 32 + nt * 8 + tc * 2 + cc);
                    if (cg == tg) g_tgt[t] = val;
                }
            }
            float s = 0.0f;
            #pragma unroll
            for (int j = 0; j < 8; j++)
                s += __expf(v[j] - m);

            // reduce across the 4 lanes of the quad (same row)
            #pragma unroll
            for (int off = 1; off <= 2; off <<= 1) {
                float m2 = __shfl_xor_sync(0xffffffffu, m, off);
                float s2 = __shfl_xor_sync(0xffffffffu, s, off);
                float mn = fmaxf(m, m2);
                s = s * __expf(m - mn) + s2 * __expf(m2 - mn);
                m = mn;
            }
            if (tc == 0) {
                spm[wn * 128 + rloc] = m;
                sps[wn * 128 + rloc] = s;
            }
        }
    }
    __syncthreads();

    // merge 4 warp-column partials per row -> global partials
    if (tid < 128) {
        float m = spm[tid], s = sps[tid];
        #pragma unroll
        for (int w = 1; w < 4; w++) {
            float m2 = spm[w * 128 + tid];
            float s2 = sps[w * 128 + tid];
            float mn = fmaxf(m, m2);
            s = s * __expf(m - mn) + s2 * __expf(m2 - mn);
            m = mn;
        }
        g_pm[chnk * BT + row0 + tid] = m;
        g_ps[chnk * BT + row0 + tid] = s;
    }
}

// ------------------------- stage 2: merge + reduce --------------------------
__global__ __launch_bounds__(256)
void reduce_kernel(const void* __restrict__ target_raw)
{
    const int t = blockIdx.x * blockDim.x + threadIdx.x;

    float m = -INFINITY, s = 0.0f;
    for (int c = 0; c < NCH; c++) {
        float mc = g_pm[c * BT + t];
        float sc = g_ps[c * BT + t];
        float mn = fmaxf(m, mc);
        s = s * expf(m - mn) + sc * expf(mc - mn);
        m = mn;
    }
    const float lse = m + logf(s);

    const long long tg = load_target(target_raw, t);
    const int valid = (tg != (long long)IGNORE_INDEX) ? 1 : 0;
    float per = valid ? (lse - g_tgt[t]) : 0.0f;

    #pragma unroll
    for (int off = 16; off >= 1; off >>= 1)
        per += __shfl_xor_sync(0xffffffffu, per, off);
    int vc = valid;
    #pragma unroll
    for (int off = 16; off >= 1; off >>= 1)
        vc += __shfl_xor_sync(0xffffffffu, vc, off);
    if ((threadIdx.x & 31) == 0) {
        atomicAdd(&g_sum, per);
        atomicAdd(&g_cnt, vc);
    }
}

__global__ void finalize_kernel(float* __restrict__ out)
{
    int c = g_cnt;
    if (c < 1) c = 1;
    out[0] = g_sum / (float)c;
}

// ------------------------- host launch --------------------------------------
extern "C" void kernel_launch(void* const* d_in, const int* in_sizes, int n_in,
                              void* d_out, int out_size)
{
    const float* x          = (const float*)d_in[0];
    const void*  target_raw = d_in[1];
    const float* w          = (const float*)d_in[2];
    const float* bias       = (const float*)d_in[3];
    float*       out        = (float*)d_out;

    cudaFuncSetAttribute(gemm_kernel, cudaFuncAttributeMaxDynamicSharedMemorySize,
                         SMEM_DYN);

    void *xb = nullptr, *wb = nullptr;
    cudaGetSymbolAddress(&xb, g_xb);
    cudaGetSymbolAddress(&wb, g_wb);

    {
        int n8 = (BT * H) / 8;
        convert_kernel<<<(n8 + 255) / 256, 256>>>(x, (__nv_bfloat16*)xb, n8);
    }
    {
        int n8 = (int)(((size_t)V * H) / 8);
        convert_kernel<<<(n8 + 255) / 256, 256>>>(w, (__nv_bfloat16*)wb, n8);
    }

    init_kernel<<<1, 256>>>(target_raw);

    dim3 grid(NTR, NCH);
    gemm_kernel<<<grid, 256, SMEM_DYN>>>(target_raw, bias);

    reduce_kernel<<<BT / 256, 256>>>(target_raw);
    finalize_kernel<<<1, 1>>>(out);
}